// round 5
// baseline (speedup 1.0000x reference)
#include <cuda_runtime.h>
#include <cstdint>

// Problem constants
#define BB      16
#define NPTS    4096
#define SS      1024
#define KNN     32
#define NCOLS   524288u   // BB*SS*KNN
#define BN_EPS  1e-5f

// ---------------------------------------------------------------------------
// Scratch (static device globals). NEVER referenced from host code — device
// code selects them via if-constexpr so no host-shadow address ever leaks.
// Buffer reuse: conv2 writes its output into g_X0 (X0 dead after conv1).
// ---------------------------------------------------------------------------
__device__ __align__(128) float g_X0[67u * NCOLS];    // gathered feats; later Y2
__device__ __align__(128) float g_Y1[64u * NCOLS];    // conv1 raw output (pre-BN)
__device__ __align__(128) float g_Y3[128u * NCOLS];   // conv3 raw output
__device__ __align__(128) int   g_ball[BB * SS * KNN];
__device__ float g_sum[128];
__device__ float g_sq[128];
__device__ float2 g_aff[128];   // per-channel BN affine (a,b): out = relu(a*y+b)

// Device-side scratch selectors (stage = which conv)
template <int STAGE> __device__ __forceinline__ const float* stage_in() {
    if constexpr (STAGE == 1) return g_X0;
    else if constexpr (STAGE == 2) return g_Y1;
    else return g_X0;               // conv3 reads Y2 (aliased into g_X0)
}
template <int STAGE> __device__ __forceinline__ float* stage_out() {
    if constexpr (STAGE == 1) return g_Y1;
    else if constexpr (STAGE == 2) return g_X0;   // Y2 aliases dead X0
    else return g_Y3;
}

// ---------------------------------------------------------------------------
// FPS: one block per batch. Points live in REGISTERS only (8 per thread);
// the next centroid is broadcast through 12 bytes of shared memory by its
// owning thread. Zero dynamic smem -> launch always legal.
// ---------------------------------------------------------------------------
__global__ void __launch_bounds__(512) fps_kernel(const float* __restrict__ xyz,
                                                  float* __restrict__ newxyz)
{
    __shared__ unsigned long long warr[16];
    __shared__ float cs[3];
    __shared__ int sf;

    int b = blockIdx.x, tid = threadIdx.x;
    const float* base = xyz + (size_t)b * NPTS * 3;

    float lx[8], ly[8], lz[8], ld[8];
#pragma unroll
    for (int i = 0; i < 8; i++) {
        int j = tid + 512 * i;
        lx[i] = base[j * 3 + 0];
        ly[i] = base[j * 3 + 1];
        lz[i] = base[j * 3 + 2];
        ld[i] = 1e10f;
    }

    if (tid == 0) { cs[0] = lx[0]; cs[1] = ly[0]; cs[2] = lz[0]; }
    __syncthreads();

    int lane = tid & 31, wid = tid >> 5;
    for (int it = 0; it < SS; ++it) {
        float cx = cs[0], cy = cs[1], cz = cs[2];
        if (tid == 0) {
            float* o = newxyz + ((size_t)b * SS + it) * 3;
            o[0] = cx; o[1] = cy; o[2] = cz;
        }
        if (it == SS - 1) break;

        float bv = -1.0f; int bj = 0;
#pragma unroll
        for (int i = 0; i < 8; i++) {
            float dx = lx[i] - cx;
            float dy = ly[i] - cy;
            float dz = lz[i] - cz;
            // per-op IEEE rounding (no fma contraction) to match reference
            float d = __fadd_rn(__fadd_rn(__fmul_rn(dx, dx), __fmul_rn(dy, dy)),
                                __fmul_rn(dz, dz));
            float nd = fminf(ld[i], d);
            ld[i] = nd;
            if (nd > bv) { bv = nd; bj = tid + 512 * i; }
        }
        // pack (value, first-index tie-break) into u64, max-reduce
        unsigned long long p =
            ((unsigned long long)__float_as_uint(bv) << 32) |
            (unsigned long long)(0xFFFFFFFFu - (unsigned)bj);
#pragma unroll
        for (int off = 16; off; off >>= 1) {
            unsigned long long q = __shfl_xor_sync(0xFFFFFFFFu, p, off);
            if (q > p) p = q;
        }
        if (lane == 0) warr[wid] = p;
        __syncthreads();
        if (wid == 0) {
            unsigned long long q = warr[lane & 15];
#pragma unroll
            for (int off = 8; off; off >>= 1) {
                unsigned long long r = __shfl_xor_sync(0xFFFFFFFFu, q, off);
                if (r > q) q = r;
            }
            if (lane == 0) sf = (int)(0xFFFFFFFFu - (unsigned)(q & 0xFFFFFFFFull));
        }
        __syncthreads();
        int f = sf;
        if ((f & 511) == tid) {
            int slot = f >> 9;
            float vx = lx[0], vy = ly[0], vz = lz[0];
#pragma unroll
            for (int i = 1; i < 8; i++)
                if (slot == i) { vx = lx[i]; vy = ly[i]; vz = lz[i]; }
            cs[0] = vx; cs[1] = vy; cs[2] = vz;
        }
        __syncthreads();
    }
}

// ---------------------------------------------------------------------------
// Ball query: replicate reference expansion formula per-op; R2 = f32(0.04).
// Dynamic smem exactly 48KB, zero static -> within default limit.
// ---------------------------------------------------------------------------
__global__ void __launch_bounds__(256) ballq_kernel(const float* __restrict__ xyz,
                                                    const float* __restrict__ newxyz)
{
    extern __shared__ float sm[];
    float* px = sm;
    float* py = sm + NPTS;
    float* pz = sm + 2 * NPTS;

    int b = blockIdx.x >> 2;
    int chunk = blockIdx.x & 3;
    const float* base = xyz + (size_t)b * NPTS * 3;
    for (int i = threadIdx.x; i < NPTS; i += 256) {
        px[i] = base[i * 3 + 0];
        py[i] = base[i * 3 + 1];
        pz[i] = base[i * 3 + 2];
    }
    __syncthreads();

    int s = chunk * 256 + threadIdx.x;
    const float* c = newxyz + ((size_t)b * SS + s) * 3;
    float sx = c[0], sy = c[1], sz = c[2];
    float ssum = __fadd_rn(__fadd_rn(__fmul_rn(sx, sx), __fmul_rn(sy, sy)),
                           __fmul_rn(sz, sz));
    int* out = g_ball + ((size_t)b * SS + s) * KNN;

    const float R2 = (float)(0.2 * 0.2);   // f32(0.04), matches JAX weak typing
    int cnt = 0, first = 0;
    for (int j = 0; j < NPTS; j++) {
        float x = px[j], y = py[j], z = pz[j];
        float dsum = __fadd_rn(__fadd_rn(__fmul_rn(x, x), __fmul_rn(y, y)),
                               __fmul_rn(z, z));
        float dot  = __fadd_rn(__fadd_rn(__fmul_rn(sx, x), __fmul_rn(sy, y)),
                               __fmul_rn(sz, z));
        float d = __fadd_rn(__fadd_rn(__fmul_rn(-2.0f, dot), ssum), dsum);
        if (!(d > R2)) {
            if (cnt == 0) first = j;
            out[cnt] = j;
            cnt++;
            if (cnt >= KNN) break;
        }
    }
    for (int i = cnt; i < KNN; i++) out[i] = first;
}

// ---------------------------------------------------------------------------
// Gather: build X0[67][NCOLS], n = (b*S+s)*K+k. (writes g_X0 device-side)
// ---------------------------------------------------------------------------
__global__ void __launch_bounds__(256) gather_kernel(const float* __restrict__ xyz,
                                                     const float* __restrict__ pts,
                                                     const float* __restrict__ newxyz)
{
    unsigned n = blockIdx.x * 256u + threadIdx.x;  // < NCOLS
    int b = n >> 15;
    int rem = n & 32767;
    int s = rem >> 5;
    int j = g_ball[n];

    const float* p = xyz + ((size_t)b * NPTS + j) * 3;
    const float* q = newxyz + ((size_t)b * SS + s) * 3;
    g_X0[n]              = p[0] - q[0];
    g_X0[NCOLS + n]      = p[1] - q[1];
    g_X0[2u * NCOLS + n] = p[2] - q[2];

    const float4* f = (const float4*)(pts + ((size_t)b * NPTS + j) * 64);
#pragma unroll
    for (int c = 0; c < 16; c++) {
        float4 v = f[c];
        size_t o = (size_t)(3 + 4 * c) * NCOLS + n;
        g_X0[o]              = v.x;
        g_X0[o + NCOLS]      = v.y;
        g_X0[o + 2u * NCOLS] = v.z;
        g_X0[o + 3u * NCOLS] = v.w;
    }
}

// ---------------------------------------------------------------------------
// Conv (1x1) as GEMM, chunked-K so dynamic smem <= 48KB, zero static smem.
// AFF => apply previous layer's BN affine + ReLU while loading X.
// ---------------------------------------------------------------------------
template <int STAGE, int CIN, int COUT, int NT, bool AFF>
__global__ void __launch_bounds__(256) conv_kernel(const float* __restrict__ Wg,
                                                   const float* __restrict__ bias)
{
    const float* __restrict__ X = stage_in<STAGE>();
    float* __restrict__ Y = stage_out<STAGE>();

    constexpr int BN = 128;
    constexpr int RT = 8;              // rows per thread
    constexpr int CG = BN / NT;        // threads per row-group
    constexpr int KC = 32;             // K chunk staged in smem
    extern __shared__ float sm[];
    float* Ws = sm;                    // [CIN][COUT] (transposed weights)
    float* Xs = sm + CIN * COUT;       // [KC][BN]

    int tid = threadIdx.x;
    size_t n0 = (size_t)blockIdx.x * BN;

    for (int i = tid; i < CIN * COUT; i += 256) {
        int o = i / CIN, c = i - o * CIN;
        Ws[c * COUT + o] = Wg[i];
    }

    int cg = tid % CG, rg = tid / CG;
    int r0 = rg * RT, c0 = cg * NT;

    float acc[RT][NT];
#pragma unroll
    for (int i = 0; i < RT; i++)
#pragma unroll
        for (int j = 0; j < NT; j++) acc[i][j] = 0.0f;

    for (int k0 = 0; k0 < CIN; k0 += KC) {
        int kc = (CIN - k0 < KC) ? (CIN - k0) : KC;
        __syncthreads();
        for (int i = tid; i < kc * BN; i += 256) {
            int c = i >> 7, col = i & 127;
            float v = X[(size_t)(k0 + c) * NCOLS + n0 + col];
            if (AFF) {
                float2 ab = g_aff[k0 + c];
                v = fmaxf(fmaf(v, ab.x, ab.y), 0.0f);
            }
            Xs[i] = v;
        }
        __syncthreads();

#pragma unroll 4
        for (int k = 0; k < kc; k++) {
            float a[RT], bv[NT];
#pragma unroll
            for (int i = 0; i < RT; i++) a[i] = Ws[(k0 + k) * COUT + r0 + i];
#pragma unroll
            for (int j = 0; j < NT; j++) bv[j] = Xs[k * BN + c0 + j];
#pragma unroll
            for (int i = 0; i < RT; i++)
#pragma unroll
                for (int j = 0; j < NT; j++) acc[i][j] += a[i] * bv[j];
        }
    }

#pragma unroll
    for (int i = 0; i < RT; i++) {
        float bsv = bias[r0 + i];
        float* yp = Y + (size_t)(r0 + i) * NCOLS + n0 + c0;
#pragma unroll
        for (int j = 0; j < NT; j += 4)
            *(float4*)(yp + j) = make_float4(acc[i][j] + bsv, acc[i][j + 1] + bsv,
                                             acc[i][j + 2] + bsv, acc[i][j + 3] + bsv);
    }
}

// ---------------------------------------------------------------------------
// BN statistics pass over the just-written Y (selected device-side).
// ---------------------------------------------------------------------------
__global__ void zero_stats()
{
    int t = threadIdx.x;
    g_sum[t] = 0.0f;
    g_sq[t]  = 0.0f;
}

template <int STAGE>
__global__ void __launch_bounds__(256) bn_stats_kernel()
{
    const float* __restrict__ Y = stage_out<STAGE>();
    __shared__ float ss[8], sq8[8];
    int c    = blockIdx.x >> 4;
    int slab = blockIdx.x & 15;
    const float4* p = (const float4*)(Y + (size_t)c * NCOLS + (size_t)slab * (NCOLS / 16));
    float s = 0.0f, q = 0.0f;
    for (int i = threadIdx.x; i < (int)(NCOLS / 64); i += 256) {   // 8192 float4s
        float4 v = p[i];
        s += (v.x + v.y) + (v.z + v.w);
        q += (v.x * v.x + v.y * v.y) + (v.z * v.z + v.w * v.w);
    }
#pragma unroll
    for (int off = 16; off; off >>= 1) {
        s += __shfl_xor_sync(0xFFFFFFFFu, s, off);
        q += __shfl_xor_sync(0xFFFFFFFFu, q, off);
    }
    if ((threadIdx.x & 31) == 0) { ss[threadIdx.x >> 5] = s; sq8[threadIdx.x >> 5] = q; }
    __syncthreads();
    if (threadIdx.x == 0) {
        float S = 0.0f, Q = 0.0f;
#pragma unroll
        for (int w = 0; w < 8; w++) { S += ss[w]; Q += sq8[w]; }
        atomicAdd(&g_sum[c], S);
        atomicAdd(&g_sq[c], Q);
    }
}

__global__ void stats_kernel(const float* __restrict__ gamma,
                             const float* __restrict__ beta, int C)
{
    int c = threadIdx.x;
    if (c < C) {
        const float inv = 1.0f / (float)NCOLS;
        float mean = g_sum[c] * inv;
        float var  = g_sq[c] * inv - mean * mean;
        float a = gamma[c] / sqrtf(var + BN_EPS);
        g_aff[c] = make_float2(a, beta[c] - mean * a);
    }
}

// ---------------------------------------------------------------------------
// Finalize: affine3 + ReLU + max over 32 samples -> new_points[b][s][o]
// ---------------------------------------------------------------------------
__global__ void __launch_bounds__(128) finalize_kernel(float* __restrict__ outp)
{
    int bs = blockIdx.x;       // (b*S + s)
    int o  = threadIdx.x;      // channel
    float2 ab = g_aff[o];
    const float4* p = (const float4*)(g_Y3 + (size_t)o * NCOLS + (size_t)bs * KNN);
    float m = 0.0f;            // relu floor
#pragma unroll
    for (int i = 0; i < 8; i++) {
        float4 v = p[i];
        m = fmaxf(m, fmaf(v.x, ab.x, ab.y));
        m = fmaxf(m, fmaf(v.y, ab.x, ab.y));
        m = fmaxf(m, fmaf(v.z, ab.x, ab.y));
        m = fmaxf(m, fmaf(v.w, ab.x, ab.y));
    }
    outp[(size_t)bs * 128 + o] = m;
}

// ---------------------------------------------------------------------------
// Launch (only harness pointers cross host->device; all smem <= 48KB,
// no cudaFuncSetAttribute anywhere)
// ---------------------------------------------------------------------------
extern "C" void kernel_launch(void* const* d_in, const int* in_sizes, int n_in,
                              void* d_out, int out_size)
{
    const float* xyz    = (const float*)d_in[0];
    const float* points = (const float*)d_in[1];
    const float* w1 = (const float*)d_in[2];
    const float* b1 = (const float*)d_in[3];
    const float* g1 = (const float*)d_in[4];
    const float* be1 = (const float*)d_in[5];
    const float* w2 = (const float*)d_in[6];
    const float* b2 = (const float*)d_in[7];
    const float* g2 = (const float*)d_in[8];
    const float* be2 = (const float*)d_in[9];
    const float* w3 = (const float*)d_in[10];
    const float* b3 = (const float*)d_in[11];
    const float* g3 = (const float*)d_in[12];
    const float* be3 = (const float*)d_in[13];

    float* out = (float*)d_out;
    float* newxyz = out;                       // 16*1024*3
    float* newpts = out + (size_t)BB * SS * 3; // 16*1024*128

    const int smem_xyz = 3 * NPTS * 4;                       // 49152 (ballq only)
    const int smem_c1  = (67 * 64 + 32 * 128) * 4;           // 33536
    const int smem_c2  = (64 * 64 + 32 * 128) * 4;           // 32768
    const int smem_c3  = (64 * 128 + 32 * 128) * 4;          // 49152

    fps_kernel<<<BB, 512>>>(xyz, newxyz);
    ballq_kernel<<<BB * 4, 256, smem_xyz>>>(xyz, newxyz);
    gather_kernel<<<NCOLS / 256, 256>>>(xyz, points, newxyz);

    conv_kernel<1, 67, 64, 4, false><<<NCOLS / 128, 256, smem_c1>>>(w1, b1);
    zero_stats<<<1, 128>>>();
    bn_stats_kernel<1><<<64 * 16, 256>>>();
    stats_kernel<<<1, 128>>>(g1, be1, 64);

    conv_kernel<2, 64, 64, 4, true><<<NCOLS / 128, 256, smem_c2>>>(w2, b2);
    zero_stats<<<1, 128>>>();
    bn_stats_kernel<2><<<64 * 16, 256>>>();
    stats_kernel<<<1, 128>>>(g2, be2, 64);

    conv_kernel<3, 64, 128, 8, true><<<NCOLS / 128, 256, smem_c3>>>(w3, b3);
    zero_stats<<<1, 128>>>();
    bn_stats_kernel<3><<<128 * 16, 256>>>();
    stats_kernel<<<1, 128>>>(g3, be3, 128);

    finalize_kernel<<<BB * SS, 128>>>(newpts);
}

// round 6
// speedup vs baseline: 1.1321x; 1.1321x over previous
#include <cuda_runtime.h>
#include <cstdint>

// Problem constants
#define BB      16
#define NPTS    4096
#define SS      1024
#define KNN     32
#define NCOLS   524288u   // BB*SS*KNN
#define NBS     16384     // BB*SS
#define BN_EPS  1e-5f

// ---------------------------------------------------------------------------
// Scratch (static device globals). Never referenced from host code.
// conv2 writes its output into g_X0 (X0 dead after conv1). No Y3 buffer:
// conv3 reduces to per-(bs,ch) max/min directly.
// ---------------------------------------------------------------------------
__device__ __align__(128) float g_X0[67u * NCOLS];    // gathered feats; later Y2
__device__ __align__(128) float g_Y1[64u * NCOLS];    // conv1 raw output (pre-BN)
__device__ __align__(128) float g_mx[NBS * 128];      // conv3 per-(bs,ch) max
__device__ __align__(128) float g_mn[NBS * 128];      // conv3 per-(bs,ch) min
__device__ __align__(128) int   g_ball[BB * SS * KNN];
__device__ float g_sum[128];
__device__ float g_sq[128];
__device__ float2 g_aff[128];   // per-channel BN affine (a,b)

template <int STAGE> __device__ __forceinline__ const float* stage_in() {
    if constexpr (STAGE == 1) return g_X0;
    else if constexpr (STAGE == 2) return g_Y1;
    else return g_X0;               // conv3 reads Y2 (aliased into g_X0)
}
template <int STAGE> __device__ __forceinline__ float* stage_out() {
    if constexpr (STAGE == 1) return g_Y1;
    else return g_X0;               // conv2 -> X0; conv3 never stores
}

// ---------------------------------------------------------------------------
// FPS: one block per batch; points in registers, centroid broadcast via smem.
// ---------------------------------------------------------------------------
__global__ void __launch_bounds__(512) fps_kernel(const float* __restrict__ xyz,
                                                  float* __restrict__ newxyz)
{
    __shared__ unsigned long long warr[16];
    __shared__ float cs[3];
    __shared__ int sf;

    int b = blockIdx.x, tid = threadIdx.x;
    const float* base = xyz + (size_t)b * NPTS * 3;

    float lx[8], ly[8], lz[8], ld[8];
#pragma unroll
    for (int i = 0; i < 8; i++) {
        int j = tid + 512 * i;
        lx[i] = base[j * 3 + 0];
        ly[i] = base[j * 3 + 1];
        lz[i] = base[j * 3 + 2];
        ld[i] = 1e10f;
    }

    if (tid == 0) { cs[0] = lx[0]; cs[1] = ly[0]; cs[2] = lz[0]; }
    __syncthreads();

    int lane = tid & 31, wid = tid >> 5;
    for (int it = 0; it < SS; ++it) {
        float cx = cs[0], cy = cs[1], cz = cs[2];
        if (tid == 0) {
            float* o = newxyz + ((size_t)b * SS + it) * 3;
            o[0] = cx; o[1] = cy; o[2] = cz;
        }
        if (it == SS - 1) break;

        float bv = -1.0f; int bj = 0;
#pragma unroll
        for (int i = 0; i < 8; i++) {
            float dx = lx[i] - cx;
            float dy = ly[i] - cy;
            float dz = lz[i] - cz;
            float d = __fadd_rn(__fadd_rn(__fmul_rn(dx, dx), __fmul_rn(dy, dy)),
                                __fmul_rn(dz, dz));
            float nd = fminf(ld[i], d);
            ld[i] = nd;
            if (nd > bv) { bv = nd; bj = tid + 512 * i; }
        }
        unsigned long long p =
            ((unsigned long long)__float_as_uint(bv) << 32) |
            (unsigned long long)(0xFFFFFFFFu - (unsigned)bj);
#pragma unroll
        for (int off = 16; off; off >>= 1) {
            unsigned long long q = __shfl_xor_sync(0xFFFFFFFFu, p, off);
            if (q > p) p = q;
        }
        if (lane == 0) warr[wid] = p;
        __syncthreads();
        if (wid == 0) {
            unsigned long long q = warr[lane & 15];
#pragma unroll
            for (int off = 8; off; off >>= 1) {
                unsigned long long r = __shfl_xor_sync(0xFFFFFFFFu, q, off);
                if (r > q) q = r;
            }
            if (lane == 0) sf = (int)(0xFFFFFFFFu - (unsigned)(q & 0xFFFFFFFFull));
        }
        __syncthreads();
        int f = sf;
        if ((f & 511) == tid) {
            int slot = f >> 9;
            float vx = lx[0], vy = ly[0], vz = lz[0];
#pragma unroll
            for (int i = 1; i < 8; i++)
                if (slot == i) { vx = lx[i]; vy = ly[i]; vz = lz[i]; }
            cs[0] = vx; cs[1] = vy; cs[2] = vz;
        }
        __syncthreads();
    }
}

// ---------------------------------------------------------------------------
// Ball query (exact reference arithmetic).
// ---------------------------------------------------------------------------
__global__ void __launch_bounds__(256) ballq_kernel(const float* __restrict__ xyz,
                                                    const float* __restrict__ newxyz)
{
    extern __shared__ float sm[];
    float* px = sm;
    float* py = sm + NPTS;
    float* pz = sm + 2 * NPTS;

    int b = blockIdx.x >> 2;
    int chunk = blockIdx.x & 3;
    const float* base = xyz + (size_t)b * NPTS * 3;
    for (int i = threadIdx.x; i < NPTS; i += 256) {
        px[i] = base[i * 3 + 0];
        py[i] = base[i * 3 + 1];
        pz[i] = base[i * 3 + 2];
    }
    __syncthreads();

    int s = chunk * 256 + threadIdx.x;
    const float* c = newxyz + ((size_t)b * SS + s) * 3;
    float sx = c[0], sy = c[1], sz = c[2];
    float ssum = __fadd_rn(__fadd_rn(__fmul_rn(sx, sx), __fmul_rn(sy, sy)),
                           __fmul_rn(sz, sz));
    int* out = g_ball + ((size_t)b * SS + s) * KNN;

    const float R2 = (float)(0.2 * 0.2);
    int cnt = 0, first = 0;
    for (int j = 0; j < NPTS; j++) {
        float x = px[j], y = py[j], z = pz[j];
        float dsum = __fadd_rn(__fadd_rn(__fmul_rn(x, x), __fmul_rn(y, y)),
                               __fmul_rn(z, z));
        float dot  = __fadd_rn(__fadd_rn(__fmul_rn(sx, x), __fmul_rn(sy, y)),
                               __fmul_rn(sz, z));
        float d = __fadd_rn(__fadd_rn(__fmul_rn(-2.0f, dot), ssum), dsum);
        if (!(d > R2)) {
            if (cnt == 0) first = j;
            out[cnt] = j;
            cnt++;
            if (cnt >= KNN) break;
        }
    }
    for (int i = cnt; i < KNN; i++) out[i] = first;
}

// ---------------------------------------------------------------------------
// Gather: build X0[67][NCOLS], n = (b*S+s)*K+k.
// ---------------------------------------------------------------------------
__global__ void __launch_bounds__(256) gather_kernel(const float* __restrict__ xyz,
                                                     const float* __restrict__ pts,
                                                     const float* __restrict__ newxyz)
{
    unsigned n = blockIdx.x * 256u + threadIdx.x;
    int b = n >> 15;
    int rem = n & 32767;
    int s = rem >> 5;
    int j = g_ball[n];

    const float* p = xyz + ((size_t)b * NPTS + j) * 3;
    const float* q = newxyz + ((size_t)b * SS + s) * 3;
    g_X0[n]              = p[0] - q[0];
    g_X0[NCOLS + n]      = p[1] - q[1];
    g_X0[2u * NCOLS + n] = p[2] - q[2];

    const float4* f = (const float4*)(pts + ((size_t)b * NPTS + j) * 64);
#pragma unroll
    for (int c = 0; c < 16; c++) {
        float4 v = f[c];
        size_t o = (size_t)(3 + 4 * c) * NCOLS + n;
        g_X0[o]              = v.x;
        g_X0[o + NCOLS]      = v.y;
        g_X0[o + 2u * NCOLS] = v.z;
        g_X0[o + 3u * NCOLS] = v.w;
    }
}

// ---------------------------------------------------------------------------
// Conv (1x1) as GEMM. BN=256 cols/block, RT=8 rows x NT=8 cols per thread,
// one warp per 8-row group (CG=32). KC=16 K-chunk in smem; all smem <= 48KB.
// AFF: apply prev BN affine + ReLU on X load. Fused epilogue:
//  - bias add
//  - per-channel sum/sumsq (full-warp shfl -> atomicAdd)
//  - MINMAX (conv3): per-(bs,ch) max/min over 32-col groups (4-lane shfl),
//    no Y store at all.
// ---------------------------------------------------------------------------
template <int STAGE, int CIN, int COUT, int THREADS, bool AFF, bool MINMAX>
__global__ void __launch_bounds__(THREADS) conv_kernel(const float* __restrict__ Wg,
                                                       const float* __restrict__ bias)
{
    const float* __restrict__ X = stage_in<STAGE>();
    float* __restrict__ Y = stage_out<STAGE>();

    constexpr int BN = 256;
    constexpr int RT = 8;
    constexpr int NT = 8;
    constexpr int KC = 16;
    extern __shared__ float sm[];
    float* Ws = sm;                    // [CIN][COUT] transposed weights
    float* Xs = sm + CIN * COUT;       // [KC][BN]

    int tid = threadIdx.x;
    size_t n0 = (size_t)blockIdx.x * BN;

    for (int i = tid; i < CIN * COUT; i += THREADS) {
        int o = i / CIN, c = i - o * CIN;
        Ws[c * COUT + o] = Wg[i];
    }

    int cg = tid & 31, rg = tid >> 5;
    int r0 = rg * RT, c0 = cg * NT;

    float acc[RT][NT];
#pragma unroll
    for (int i = 0; i < RT; i++)
#pragma unroll
        for (int j = 0; j < NT; j++) acc[i][j] = 0.0f;

    for (int k0 = 0; k0 < CIN; k0 += KC) {
        int kc = (CIN - k0 < KC) ? (CIN - k0) : KC;
        __syncthreads();
        for (int i = tid; i < kc * (BN / 4); i += THREADS) {
            int c = i / (BN / 4), col4 = i - c * (BN / 4);
            float4 v = *(const float4*)(X + (size_t)(k0 + c) * NCOLS + n0 + col4 * 4);
            if (AFF) {
                float2 ab = g_aff[k0 + c];
                v.x = fmaxf(fmaf(v.x, ab.x, ab.y), 0.0f);
                v.y = fmaxf(fmaf(v.y, ab.x, ab.y), 0.0f);
                v.z = fmaxf(fmaf(v.z, ab.x, ab.y), 0.0f);
                v.w = fmaxf(fmaf(v.w, ab.x, ab.y), 0.0f);
            }
            *(float4*)(Xs + c * BN + col4 * 4) = v;
        }
        __syncthreads();

#pragma unroll 4
        for (int k = 0; k < kc; k++) {
            float a[RT], bv[NT];
#pragma unroll
            for (int i = 0; i < RT; i++) a[i] = Ws[(k0 + k) * COUT + r0 + i];
#pragma unroll
            for (int j = 0; j < NT; j++) bv[j] = Xs[k * BN + c0 + j];
#pragma unroll
            for (int i = 0; i < RT; i++)
#pragma unroll
                for (int j = 0; j < NT; j++) acc[i][j] += a[i] * bv[j];
        }
    }

    // ---- epilogue: bias, (optional) store, stats, (optional) minmax ----
    float ps[RT], pq[RT];
#pragma unroll
    for (int i = 0; i < RT; i++) {
        float bsv = bias[r0 + i];
        ps[i] = 0.0f; pq[i] = 0.0f;
#pragma unroll
        for (int j = 0; j < NT; j++) {
            float v = acc[i][j] + bsv;
            acc[i][j] = v;
            ps[i] += v;
            pq[i] += v * v;
        }
        if (!MINMAX) {
            float* yp = Y + (size_t)(r0 + i) * NCOLS + n0 + c0;
            *(float4*)(yp)     = make_float4(acc[i][0], acc[i][1], acc[i][2], acc[i][3]);
            *(float4*)(yp + 4) = make_float4(acc[i][4], acc[i][5], acc[i][6], acc[i][7]);
        }
    }

    // full-warp reduce of channel partials (each warp owns rows r0..r0+7)
#pragma unroll
    for (int off = 16; off; off >>= 1) {
#pragma unroll
        for (int i = 0; i < RT; i++) {
            ps[i] += __shfl_xor_sync(0xFFFFFFFFu, ps[i], off);
            pq[i] += __shfl_xor_sync(0xFFFFFFFFu, pq[i], off);
        }
    }
    if (cg == 0) {
#pragma unroll
        for (int i = 0; i < RT; i++) {
            atomicAdd(&g_sum[r0 + i], ps[i]);
            atomicAdd(&g_sq[r0 + i], pq[i]);
        }
    }

    if (MINMAX) {
        // thread's 8 cols lie inside one 32-col (bs) group; 4 lanes per group
        float mx[RT], mn[RT];
#pragma unroll
        for (int i = 0; i < RT; i++) {
            float a0 = fmaxf(fmaxf(acc[i][0], acc[i][1]), fmaxf(acc[i][2], acc[i][3]));
            float a1 = fmaxf(fmaxf(acc[i][4], acc[i][5]), fmaxf(acc[i][6], acc[i][7]));
            mx[i] = fmaxf(a0, a1);
            float b0 = fminf(fminf(acc[i][0], acc[i][1]), fminf(acc[i][2], acc[i][3]));
            float b1 = fminf(fminf(acc[i][4], acc[i][5]), fminf(acc[i][6], acc[i][7]));
            mn[i] = fminf(b0, b1);
        }
#pragma unroll
        for (int off = 1; off <= 2; off <<= 1) {
#pragma unroll
            for (int i = 0; i < RT; i++) {
                mx[i] = fmaxf(mx[i], __shfl_xor_sync(0xFFFFFFFFu, mx[i], off));
                mn[i] = fminf(mn[i], __shfl_xor_sync(0xFFFFFFFFu, mn[i], off));
            }
        }
        if ((cg & 3) == 0) {
            size_t bs = n0 / KNN + (cg >> 2);
#pragma unroll
            for (int i = 0; i < RT; i++) {
                g_mx[bs * 128 + r0 + i] = mx[i];
                g_mn[bs * 128 + r0 + i] = mn[i];
            }
        }
    }
}

// ---------------------------------------------------------------------------
// Stats reset + stats -> affine
// ---------------------------------------------------------------------------
__global__ void zero_stats()
{
    int t = threadIdx.x;
    g_sum[t] = 0.0f;
    g_sq[t]  = 0.0f;
}

__global__ void stats_kernel(const float* __restrict__ gamma,
                             const float* __restrict__ beta, int C)
{
    int c = threadIdx.x;
    if (c < C) {
        const float inv = 1.0f / (float)NCOLS;
        float mean = g_sum[c] * inv;
        float var  = g_sq[c] * inv - mean * mean;
        float a = gamma[c] / sqrtf(var + BN_EPS);
        g_aff[c] = make_float2(a, beta[c] - mean * a);
    }
}

// ---------------------------------------------------------------------------
// Finalize: out[bs][ch] = relu(a * (a>=0 ? mx : mn) + b)
// ---------------------------------------------------------------------------
__global__ void __launch_bounds__(256) finalize_kernel(float* __restrict__ outp)
{
    int idx = blockIdx.x * 256 + threadIdx.x;   // < NBS*128
    int ch = idx & 127;
    float2 ab = g_aff[ch];
    float v = (ab.x >= 0.0f) ? g_mx[idx] : g_mn[idx];
    outp[idx] = fmaxf(fmaf(v, ab.x, ab.y), 0.0f);
}

// ---------------------------------------------------------------------------
// Launch (only harness pointers cross host->device; all smem <= 48KB)
// ---------------------------------------------------------------------------
extern "C" void kernel_launch(void* const* d_in, const int* in_sizes, int n_in,
                              void* d_out, int out_size)
{
    const float* xyz    = (const float*)d_in[0];
    const float* points = (const float*)d_in[1];
    const float* w1 = (const float*)d_in[2];
    const float* b1 = (const float*)d_in[3];
    const float* g1 = (const float*)d_in[4];
    const float* be1 = (const float*)d_in[5];
    const float* w2 = (const float*)d_in[6];
    const float* b2 = (const float*)d_in[7];
    const float* g2 = (const float*)d_in[8];
    const float* be2 = (const float*)d_in[9];
    const float* w3 = (const float*)d_in[10];
    const float* b3 = (const float*)d_in[11];
    const float* g3 = (const float*)d_in[12];
    const float* be3 = (const float*)d_in[13];

    float* out = (float*)d_out;
    float* newxyz = out;                       // 16*1024*3
    float* newpts = out + (size_t)BB * SS * 3; // 16*1024*128

    const int smem_xyz = 3 * NPTS * 4;                       // 49152 (ballq)
    const int smem_c1  = (67 * 64 + 16 * 256) * 4;           // 33536
    const int smem_c2  = (64 * 64 + 16 * 256) * 4;           // 32768
    const int smem_c3  = (64 * 128 + 16 * 256) * 4;          // 49152

    fps_kernel<<<BB, 512>>>(xyz, newxyz);
    ballq_kernel<<<BB * 4, 256, smem_xyz>>>(xyz, newxyz);
    gather_kernel<<<NCOLS / 256, 256>>>(xyz, points, newxyz);

    zero_stats<<<1, 128>>>();
    conv_kernel<1, 67, 64, 256, false, false><<<NCOLS / 256, 256, smem_c1>>>(w1, b1);
    stats_kernel<<<1, 128>>>(g1, be1, 64);

    zero_stats<<<1, 128>>>();
    conv_kernel<2, 64, 64, 256, true, false><<<NCOLS / 256, 256, smem_c2>>>(w2, b2);
    stats_kernel<<<1, 128>>>(g2, be2, 64);

    zero_stats<<<1, 128>>>();
    conv_kernel<3, 64, 128, 512, true, true><<<NCOLS / 256, 512, smem_c3>>>(w3, b3);
    stats_kernel<<<1, 128>>>(g3, be3, 128);

    finalize_kernel<<<NBS * 128 / 256, 256>>>(newpts);
}

// round 8
// speedup vs baseline: 1.3218x; 1.1676x over previous
#include <cuda_runtime.h>
#include <cstdint>

#define BB      16
#define NPTS    4096
#define SS      1024
#define KNN     32
#define NCOLS   524288u   // BB*SS*KNN
#define NBS     16384     // BB*SS
#define BN_EPS  1e-5f

// ---------------------------------------------------------------------------
// Scratch (device globals; never referenced from host code).
// ---------------------------------------------------------------------------
__device__ __align__(128) float g_Y1[64u * NCOLS];    // conv1 out (pre-BN)
__device__ __align__(128) float g_Y2[64u * NCOLS];    // conv2 out (pre-BN)
__device__ __align__(128) float g_mx[NBS * 128];      // conv3 per-(bs,ch) max
__device__ __align__(128) float g_mn[NBS * 128];      // conv3 per-(bs,ch) min
__device__ __align__(128) int   g_ball[BB * SS * KNN];
__device__ float g_sum[128];
__device__ float g_sq[128];
__device__ float2 g_aff[128];

template <int STAGE> __device__ __forceinline__ const float* stage_in() {
    if constexpr (STAGE == 2) return g_Y1;
    else return g_Y2;
}
template <int STAGE> __device__ __forceinline__ float* stage_out() {
    if constexpr (STAGE == 2) return g_Y2;
    else return g_Y2;   // conv3 never stores Y
}

// ---------------------------------------------------------------------------
// FPS: one block/batch, points in registers, redux.sync reductions,
// ONE __syncthreads per iteration (double-buffered warp results).
// ---------------------------------------------------------------------------
__global__ void __launch_bounds__(512) fps_kernel(const float* __restrict__ xyz,
                                                  float* __restrict__ newxyz)
{
    __shared__ unsigned wv[2][16], wi[2][16];

    int b = blockIdx.x, tid = threadIdx.x;
    if (b == 0 && tid < 128) { g_sum[tid] = 0.0f; g_sq[tid] = 0.0f; }

    const float* base = xyz + (size_t)b * NPTS * 3;

    float lx[8], ly[8], lz[8], ld[8];
#pragma unroll
    for (int i = 0; i < 8; i++) {
        int j = tid + 512 * i;
        lx[i] = base[j * 3 + 0];
        ly[i] = base[j * 3 + 1];
        lz[i] = base[j * 3 + 2];
        ld[i] = 1e10f;
    }

    int lane = tid & 31, wid = tid >> 5;
    int f = 0;
    for (int it = 0; it < SS; ++it) {
        float cx = __ldg(base + f * 3 + 0);
        float cy = __ldg(base + f * 3 + 1);
        float cz = __ldg(base + f * 3 + 2);
        if (tid == 0) {
            float* o = newxyz + ((size_t)b * SS + it) * 3;
            o[0] = cx; o[1] = cy; o[2] = cz;
        }
        if (it == SS - 1) break;

        float bv = -1.0f; int bj = 0;
#pragma unroll
        for (int i = 0; i < 8; i++) {
            float dx = lx[i] - cx;
            float dy = ly[i] - cy;
            float dz = lz[i] - cz;
            // per-op IEEE rounding to match reference bit-exactly
            float d = __fadd_rn(__fadd_rn(__fmul_rn(dx, dx), __fmul_rn(dy, dy)),
                                __fmul_rn(dz, dz));
            float nd = fminf(ld[i], d);
            ld[i] = nd;
            if (nd > bv) { bv = nd; bj = tid + 512 * i; }
        }
        // warp reduce: max value (float>=0 bits monotonic), min index on ties
        unsigned vb   = __float_as_uint(bv);
        unsigned vmax = __reduce_max_sync(0xFFFFFFFFu, vb);
        unsigned cand = (vb == vmax) ? (unsigned)bj : 0xFFFFFFFFu;
        unsigned imin = __reduce_min_sync(0xFFFFFFFFu, cand);

        int pb = it & 1;
        if (lane == 0) { wv[pb][wid] = vmax; wi[pb][wid] = imin; }
        __syncthreads();

        // every warp redundantly reduces the 16 warp results -> f everywhere
        unsigned v2 = (lane < 16) ? wv[pb][lane] : 0u;
        unsigned i2 = (lane < 16) ? wi[pb][lane] : 0xFFFFFFFFu;
        unsigned vm2 = __reduce_max_sync(0xFFFFFFFFu, v2);
        unsigned c2  = (v2 == vm2) ? i2 : 0xFFFFFFFFu;
        f = (int)__reduce_min_sync(0xFFFFFFFFu, c2);
    }
}

// ---------------------------------------------------------------------------
// Ball query (exact reference arithmetic). 48KB dynamic smem, 0 static.
// ---------------------------------------------------------------------------
__global__ void __launch_bounds__(256) ballq_kernel(const float* __restrict__ xyz,
                                                    const float* __restrict__ newxyz)
{
    extern __shared__ float sm[];
    float* px = sm;
    float* py = sm + NPTS;
    float* pz = sm + 2 * NPTS;

    int b = blockIdx.x >> 2;
    int chunk = blockIdx.x & 3;
    const float* base = xyz + (size_t)b * NPTS * 3;
    for (int i = threadIdx.x; i < NPTS; i += 256) {
        px[i] = base[i * 3 + 0];
        py[i] = base[i * 3 + 1];
        pz[i] = base[i * 3 + 2];
    }
    __syncthreads();

    int s = chunk * 256 + threadIdx.x;
    const float* c = newxyz + ((size_t)b * SS + s) * 3;
    float sx = c[0], sy = c[1], sz = c[2];
    float ssum = __fadd_rn(__fadd_rn(__fmul_rn(sx, sx), __fmul_rn(sy, sy)),
                           __fmul_rn(sz, sz));
    int* out = g_ball + ((size_t)b * SS + s) * KNN;

    const float R2 = (float)(0.2 * 0.2);
    int cnt = 0, first = 0;
    for (int j = 0; j < NPTS; j++) {
        float x = px[j], y = py[j], z = pz[j];
        float dsum = __fadd_rn(__fadd_rn(__fmul_rn(x, x), __fmul_rn(y, y)),
                               __fmul_rn(z, z));
        float dot  = __fadd_rn(__fadd_rn(__fmul_rn(sx, x), __fmul_rn(sy, y)),
                               __fmul_rn(sz, z));
        float d = __fadd_rn(__fadd_rn(__fmul_rn(-2.0f, dot), ssum), dsum);
        if (!(d > R2)) {
            if (cnt == 0) first = j;
            out[cnt] = j;
            cnt++;
            if (cnt >= KNN) break;
        }
    }
    for (int i = cnt; i < KNN; i++) out[i] = first;
}

// ---------------------------------------------------------------------------
// conv1 with FUSED GATHER: no X0 buffer. Block = 256 columns (8 samples).
// Chunks: {xyz diff: 3ch} then 4 x {16 pts channels, float4-aligned}.
// RACE FIX: sq is read only AFTER the barrier that orders its writes.
// ---------------------------------------------------------------------------
__global__ void __launch_bounds__(256) conv1_kernel(const float* __restrict__ xyz,
                                                    const float* __restrict__ pts,
                                                    const float* __restrict__ newxyz,
                                                    const float* __restrict__ Wg,
                                                    const float* __restrict__ bias)
{
    constexpr int CIN = 67, COUT = 64, BN = 256, RT = 8, NT = 8;
    extern __shared__ float sm[];
    float* Ws = sm;                 // [67][64] transposed weights
    float* Xs = sm + CIN * COUT;    // [16][256]
    __shared__ float sq[8][3];

    int tid = threadIdx.x;
    size_t n0 = (size_t)blockIdx.x * BN;
    int b = (int)(n0 >> 15);

    // per-column gather state
    int j = g_ball[n0 + tid];
    const float4* prow4 = (const float4*)(pts + ((size_t)b * NPTS + j) * 64);
    if (tid < 8) {
        int s = (int)((n0 & 32767) >> 5) + tid;
        const float* q = newxyz + ((size_t)b * SS + s) * 3;
        sq[tid][0] = q[0]; sq[tid][1] = q[1]; sq[tid][2] = q[2];
    }
    for (int i = tid; i < CIN * COUT; i += 256) {
        int o = i / CIN, c = i - o * CIN;
        Ws[c * COUT + o] = Wg[i];
    }

    int cg = tid & 31, rg = tid >> 5;
    int r0 = rg * RT, c0 = cg * NT;

    float acc[RT][NT];
#pragma unroll
    for (int i = 0; i < RT; i++)
#pragma unroll
        for (int jj = 0; jj < NT; jj++) acc[i][jj] = 0.0f;

    // ---- chunk 0: xyz difference channels (k = 0..2) ----
    {
        const float* p = xyz + ((size_t)b * NPTS + j) * 3;
        float x0 = p[0], x1 = p[1], x2 = p[2];
        __syncthreads();            // Ws AND sq writes ordered before reads
        float qx = sq[rg][0], qy = sq[rg][1], qz = sq[rg][2];
        Xs[0 * BN + tid] = x0 - qx;
        Xs[1 * BN + tid] = x1 - qy;
        Xs[2 * BN + tid] = x2 - qz;
        __syncthreads();
#pragma unroll
        for (int k = 0; k < 3; k++) {
            float a[RT], bv[NT];
#pragma unroll
            for (int i = 0; i < RT; i++) a[i] = Ws[k * COUT + r0 + i];
#pragma unroll
            for (int jj = 0; jj < NT; jj++) bv[jj] = Xs[k * BN + c0 + jj];
#pragma unroll
            for (int i = 0; i < RT; i++)
#pragma unroll
                for (int jj = 0; jj < NT; jj++) acc[i][jj] += a[i] * bv[jj];
        }
    }

    // ---- chunks 1..4: 16 pts channels each (k = 3+16c .. 18+16c) ----
    for (int c4 = 0; c4 < 4; c4++) {
        int k0 = 3 + 16 * c4;
        float4 v0 = prow4[c4 * 4 + 0];
        float4 v1 = prow4[c4 * 4 + 1];
        float4 v2 = prow4[c4 * 4 + 2];
        float4 v3 = prow4[c4 * 4 + 3];
        __syncthreads();
        Xs[ 0 * BN + tid] = v0.x; Xs[ 1 * BN + tid] = v0.y;
        Xs[ 2 * BN + tid] = v0.z; Xs[ 3 * BN + tid] = v0.w;
        Xs[ 4 * BN + tid] = v1.x; Xs[ 5 * BN + tid] = v1.y;
        Xs[ 6 * BN + tid] = v1.z; Xs[ 7 * BN + tid] = v1.w;
        Xs[ 8 * BN + tid] = v2.x; Xs[ 9 * BN + tid] = v2.y;
        Xs[10 * BN + tid] = v2.z; Xs[11 * BN + tid] = v2.w;
        Xs[12 * BN + tid] = v3.x; Xs[13 * BN + tid] = v3.y;
        Xs[14 * BN + tid] = v3.z; Xs[15 * BN + tid] = v3.w;
        __syncthreads();
#pragma unroll 4
        for (int kk = 0; kk < 16; kk++) {
            int k = k0 + kk;
            float a[RT], bv[NT];
#pragma unroll
            for (int i = 0; i < RT; i++) a[i] = Ws[k * COUT + r0 + i];
#pragma unroll
            for (int jj = 0; jj < NT; jj++) bv[jj] = Xs[kk * BN + c0 + jj];
#pragma unroll
            for (int i = 0; i < RT; i++)
#pragma unroll
                for (int jj = 0; jj < NT; jj++) acc[i][jj] += a[i] * bv[jj];
        }
    }

    // ---- epilogue: bias, store Y1, fused stats ----
    float ps[RT], pq[RT];
#pragma unroll
    for (int i = 0; i < RT; i++) {
        float bsv = bias[r0 + i];
        ps[i] = 0.0f; pq[i] = 0.0f;
#pragma unroll
        for (int jj = 0; jj < NT; jj++) {
            float v = acc[i][jj] + bsv;
            acc[i][jj] = v;
            ps[i] += v;
            pq[i] += v * v;
        }
        float* yp = g_Y1 + (size_t)(r0 + i) * NCOLS + n0 + c0;
        *(float4*)(yp)     = make_float4(acc[i][0], acc[i][1], acc[i][2], acc[i][3]);
        *(float4*)(yp + 4) = make_float4(acc[i][4], acc[i][5], acc[i][6], acc[i][7]);
    }
#pragma unroll
    for (int off = 16; off; off >>= 1) {
#pragma unroll
        for (int i = 0; i < RT; i++) {
            ps[i] += __shfl_xor_sync(0xFFFFFFFFu, ps[i], off);
            pq[i] += __shfl_xor_sync(0xFFFFFFFFu, pq[i], off);
        }
    }
    if (cg == 0) {
#pragma unroll
        for (int i = 0; i < RT; i++) {
            atomicAdd(&g_sum[r0 + i], ps[i]);
            atomicAdd(&g_sq[r0 + i], pq[i]);
        }
    }
}

// ---------------------------------------------------------------------------
// conv2/conv3 GEMM: BN=256, RT=8, NT=8, KC=16, fused stats;
// conv3 additionally reduces per-(bs,ch) max/min, stores no Y.
// ---------------------------------------------------------------------------
template <int STAGE, int CIN, int COUT, int THREADS, bool MINMAX>
__global__ void __launch_bounds__(THREADS) conv_kernel(const float* __restrict__ Wg,
                                                       const float* __restrict__ bias)
{
    const float* __restrict__ X = stage_in<STAGE>();
    float* __restrict__ Y = stage_out<STAGE>();

    constexpr int BN = 256, RT = 8, NT = 8, KC = 16;
    extern __shared__ float sm[];
    float* Ws = sm;
    float* Xs = sm + CIN * COUT;

    int tid = threadIdx.x;
    size_t n0 = (size_t)blockIdx.x * BN;

    for (int i = tid; i < CIN * COUT; i += THREADS) {
        int o = i / CIN, c = i - o * CIN;
        Ws[c * COUT + o] = Wg[i];
    }

    int cg = tid & 31, rg = tid >> 5;
    int r0 = rg * RT, c0 = cg * NT;

    float acc[RT][NT];
#pragma unroll
    for (int i = 0; i < RT; i++)
#pragma unroll
        for (int j = 0; j < NT; j++) acc[i][j] = 0.0f;

    for (int k0 = 0; k0 < CIN; k0 += KC) {
        __syncthreads();
        for (int i = tid; i < KC * (BN / 4); i += THREADS) {
            int c = i / (BN / 4), col4 = i - c * (BN / 4);
            float4 v = *(const float4*)(X + (size_t)(k0 + c) * NCOLS + n0 + col4 * 4);
            float2 ab = g_aff[k0 + c];
            v.x = fmaxf(fmaf(v.x, ab.x, ab.y), 0.0f);
            v.y = fmaxf(fmaf(v.y, ab.x, ab.y), 0.0f);
            v.z = fmaxf(fmaf(v.z, ab.x, ab.y), 0.0f);
            v.w = fmaxf(fmaf(v.w, ab.x, ab.y), 0.0f);
            *(float4*)(Xs + c * BN + col4 * 4) = v;
        }
        __syncthreads();

#pragma unroll 4
        for (int k = 0; k < KC; k++) {
            float a[RT], bv[NT];
#pragma unroll
            for (int i = 0; i < RT; i++) a[i] = Ws[(k0 + k) * COUT + r0 + i];
#pragma unroll
            for (int j = 0; j < NT; j++) bv[j] = Xs[k * BN + c0 + j];
#pragma unroll
            for (int i = 0; i < RT; i++)
#pragma unroll
                for (int j = 0; j < NT; j++) acc[i][j] += a[i] * bv[j];
        }
    }

    float ps[RT], pq[RT];
#pragma unroll
    for (int i = 0; i < RT; i++) {
        float bsv = bias[r0 + i];
        ps[i] = 0.0f; pq[i] = 0.0f;
#pragma unroll
        for (int j = 0; j < NT; j++) {
            float v = acc[i][j] + bsv;
            acc[i][j] = v;
            ps[i] += v;
            pq[i] += v * v;
        }
        if (!MINMAX) {
            float* yp = Y + (size_t)(r0 + i) * NCOLS + n0 + c0;
            *(float4*)(yp)     = make_float4(acc[i][0], acc[i][1], acc[i][2], acc[i][3]);
            *(float4*)(yp + 4) = make_float4(acc[i][4], acc[i][5], acc[i][6], acc[i][7]);
        }
    }
#pragma unroll
    for (int off = 16; off; off >>= 1) {
#pragma unroll
        for (int i = 0; i < RT; i++) {
            ps[i] += __shfl_xor_sync(0xFFFFFFFFu, ps[i], off);
            pq[i] += __shfl_xor_sync(0xFFFFFFFFu, pq[i], off);
        }
    }
    if (cg == 0) {
#pragma unroll
        for (int i = 0; i < RT; i++) {
            atomicAdd(&g_sum[r0 + i], ps[i]);
            atomicAdd(&g_sq[r0 + i], pq[i]);
        }
    }

    if (MINMAX) {
        float mx[RT], mn[RT];
#pragma unroll
        for (int i = 0; i < RT; i++) {
            float a0 = fmaxf(fmaxf(acc[i][0], acc[i][1]), fmaxf(acc[i][2], acc[i][3]));
            float a1 = fmaxf(fmaxf(acc[i][4], acc[i][5]), fmaxf(acc[i][6], acc[i][7]));
            mx[i] = fmaxf(a0, a1);
            float b0 = fminf(fminf(acc[i][0], acc[i][1]), fminf(acc[i][2], acc[i][3]));
            float b1 = fminf(fminf(acc[i][4], acc[i][5]), fminf(acc[i][6], acc[i][7]));
            mn[i] = fminf(b0, b1);
        }
#pragma unroll
        for (int off = 1; off <= 2; off <<= 1) {
#pragma unroll
            for (int i = 0; i < RT; i++) {
                mx[i] = fmaxf(mx[i], __shfl_xor_sync(0xFFFFFFFFu, mx[i], off));
                mn[i] = fminf(mn[i], __shfl_xor_sync(0xFFFFFFFFu, mn[i], off));
            }
        }
        if ((cg & 3) == 0) {
            size_t bs = n0 / KNN + (cg >> 2);
#pragma unroll
            for (int i = 0; i < RT; i++) {
                g_mx[bs * 128 + r0 + i] = mx[i];
                g_mn[bs * 128 + r0 + i] = mn[i];
            }
        }
    }
}

// ---------------------------------------------------------------------------
// stats -> affine; re-zeros the accumulators for the next stage.
// ---------------------------------------------------------------------------
__global__ void stats_kernel(const float* __restrict__ gamma,
                             const float* __restrict__ beta, int C)
{
    int c = threadIdx.x;
    if (c < C) {
        const float inv = 1.0f / (float)NCOLS;
        float mean = g_sum[c] * inv;
        float var  = g_sq[c] * inv - mean * mean;
        float a = gamma[c] / sqrtf(var + BN_EPS);
        g_aff[c] = make_float2(a, beta[c] - mean * a);
    }
    g_sum[c] = 0.0f;
    g_sq[c]  = 0.0f;
}

// ---------------------------------------------------------------------------
// Finalize: out[bs][ch] = relu(a * (a>=0 ? mx : mn) + b)
// ---------------------------------------------------------------------------
__global__ void __launch_bounds__(256) finalize_kernel(float* __restrict__ outp)
{
    int idx = blockIdx.x * 256 + threadIdx.x;
    int ch = idx & 127;
    float2 ab = g_aff[ch];
    float v = (ab.x >= 0.0f) ? g_mx[idx] : g_mn[idx];
    outp[idx] = fmaxf(fmaf(v, ab.x, ab.y), 0.0f);
}

// ---------------------------------------------------------------------------
// Launch
// ---------------------------------------------------------------------------
extern "C" void kernel_launch(void* const* d_in, const int* in_sizes, int n_in,
                              void* d_out, int out_size)
{
    const float* xyz    = (const float*)d_in[0];
    const float* points = (const float*)d_in[1];
    const float* w1 = (const float*)d_in[2];
    const float* b1 = (const float*)d_in[3];
    const float* g1 = (const float*)d_in[4];
    const float* be1 = (const float*)d_in[5];
    const float* w2 = (const float*)d_in[6];
    const float* b2 = (const float*)d_in[7];
    const float* g2 = (const float*)d_in[8];
    const float* be2 = (const float*)d_in[9];
    const float* w3 = (const float*)d_in[10];
    const float* b3 = (const float*)d_in[11];
    const float* g3 = (const float*)d_in[12];
    const float* be3 = (const float*)d_in[13];

    float* out = (float*)d_out;
    float* newxyz = out;
    float* newpts = out + (size_t)BB * SS * 3;

    const int smem_xyz = 3 * NPTS * 4;                       // 49152 (ballq)
    const int smem_c1  = (67 * 64 + 16 * 256) * 4;           // 33536
    const int smem_c2  = (64 * 64 + 16 * 256) * 4;           // 32768
    const int smem_c3  = (64 * 128 + 16 * 256) * 4;          // 49152

    fps_kernel<<<BB, 512>>>(xyz, newxyz);
    ballq_kernel<<<BB * 4, 256, smem_xyz>>>(xyz, newxyz);

    conv1_kernel<<<NCOLS / 256, 256, smem_c1>>>(xyz, points, newxyz, w1, b1);
    stats_kernel<<<1, 128>>>(g1, be1, 64);

    conv_kernel<2, 64, 64, 256, false><<<NCOLS / 256, 256, smem_c2>>>(w2, b2);
    stats_kernel<<<1, 128>>>(g2, be2, 64);

    conv_kernel<3, 64, 128, 512, true><<<NCOLS / 256, 512, smem_c3>>>(w3, b3);
    stats_kernel<<<1, 128>>>(g3, be3, 128);

    finalize_kernel<<<NBS * 128 / 256, 256>>>(newpts);
}